// round 17
// baseline (speedup 1.0000x reference)
#include <cuda_runtime.h>
#include <cstdint>

#define Fdim 16
#define Sdim 512
#define Odim 32
#define Bdim 256
#define NCH  32   // number of shift-chunks
#define SC   16   // shifts per chunk (Sdim / NCH)
#define BT   16   // batch rows per block
#define NBT  16   // Bdim / BT
#define SF   (Sdim * Fdim)

// Partial maxima, float4-packed: [ch][b][fg=4][o=32] float4(f0..f3) = 16.8 MB
__device__ float4 g_partial[NCH * Bdim * 4 * Odim];

// trailing no-op: 3-launch stream so ncu captures position 0 = k1
__global__ void knop() {}

// ---------------------------------------------------------------------------
// Kernel 1: partial[ch][b][f][o] = max_{s in chunk} x[b,s,f] * W[s,f,o]
// 256 threads = o(32) x fg(4) x bh(2 halves of 8 rows).
// 48 KB smem -> 4 blocks/SM (32 warps) AND 64 regs/thread.
// ---------------------------------------------------------------------------
__global__ __launch_bounds__(256, 4) void k1_partial(const float* __restrict__ x,
                                                     const float* __restrict__ W) {
    extern __shared__ float sm[];
    float* xs = sm;                    // [BT][SC][Fdim]  = 4096 floats (16 KB)
    float* ws = sm + BT * SC * Fdim;   // [SC][Fdim][Odim]= 8192 floats (32 KB)

    const int tid   = threadIdx.x;
    const int btile = blockIdx.x;      // 0..NBT-1
    const int ch    = blockIdx.y;      // 0..NCH-1

    // ---- stage x tile: 16 rows x 256 contiguous floats, float4 copy ----
    #pragma unroll
    for (int it = 0; it < 4; ++it) {
        int idx = tid + it * 256;          // 0..1023 float4s
        int b   = idx >> 6;                // 64 float4 per row
        int t   = idx & 63;
        float4 v = *(const float4*)(x + (size_t)(btile * BT + b) * SF
                                      + ch * SC * Fdim + t * 4);
        *(float4*)(xs + b * (SC * Fdim) + t * 4) = v;   // conflict-free
    }

    // ---- stage W tile: contiguous 32 KB float4 copy ----
    {
        const float4* wsrc = (const float4*)(W + (size_t)ch * SC * Fdim * Odim);
        #pragma unroll
        for (int it = 0; it < 8; ++it) {
            int idx = tid + it * 256;      // 0..2047 float4s
            ((float4*)ws)[idx] = wsrc[idx];
        }
    }
    __syncthreads();

    // thread handles (o, f0..f0+3, 8 rows b0..b0+7)
    const int o  = tid & 31;
    const int f0 = ((tid >> 5) & 3) * 4;
    const int b0 = (tid >> 7) * 8;

    const float NEG = __int_as_float(0xff800000);   // -inf
    float4 acc[8];
    #pragma unroll
    for (int i = 0; i < 8; ++i) acc[i] = make_float4(NEG, NEG, NEG, NEG);

    #pragma unroll 2
    for (int s = 0; s < SC; ++s) {
        // W reads: stride-1 across warp (o in lanes) -> conflict-free scalar LDS
        const float w0 = ws[(s * Fdim + f0 + 0) * Odim + o];
        const float w1 = ws[(s * Fdim + f0 + 1) * Odim + o];
        const float w2 = ws[(s * Fdim + f0 + 2) * Odim + o];
        const float w3 = ws[(s * Fdim + f0 + 3) * Odim + o];
        #pragma unroll
        for (int i = 0; i < 8; ++i) {
            // uniform address across warp -> broadcast LDS.128
            const float4 xv = *(const float4*)(xs + ((b0 + i) * SC + s) * Fdim + f0);
            acc[i].x = fmaxf(acc[i].x, xv.x * w0);
            acc[i].y = fmaxf(acc[i].y, xv.y * w1);
            acc[i].z = fmaxf(acc[i].z, xv.z * w2);
            acc[i].w = fmaxf(acc[i].w, xv.w * w3);
        }
    }

    // ---- store partials: 8 coalesced STG.128 (f4-packed layout) ----
    const int fg = f0 >> 2;
    #pragma unroll
    for (int i = 0; i < 8; ++i) {
        const int bglob = btile * BT + b0 + i;
        g_partial[((size_t)(ch * Bdim + bglob) * 4 + fg) * Odim + o] = acc[i];
    }
}

// ---------------------------------------------------------------------------
// Kernel 2: out[b,o] = relu( bias[o] + sum_f max_ch partial )
// 256 blocks x 128 threads; thread = (fg, o): one float4 per chunk (MLP=32).
// ---------------------------------------------------------------------------
__global__ __launch_bounds__(128) void k2_reduce(const float* __restrict__ bias,
                                                 float* __restrict__ out) {
    const int b  = blockIdx.x;
    const int t  = threadIdx.x;
    const int fg = t >> 5;
    const int o  = t & 31;

    const float NEG = __int_as_float(0xff800000);
    float4 m = make_float4(NEG, NEG, NEG, NEG);

    const float4* base = g_partial + (size_t)b * 128 + t;
    #pragma unroll
    for (int c = 0; c < NCH; ++c) {
        float4 v = __ldcg(base + (size_t)c * (Bdim * 128));
        m.x = fmaxf(m.x, v.x); m.y = fmaxf(m.y, v.y);
        m.z = fmaxf(m.z, v.z); m.w = fmaxf(m.w, v.w);
    }

    __shared__ float red[4][Odim + 1];
    red[fg][o] = (m.x + m.y) + (m.z + m.w);
    __syncthreads();

    if (t < Odim) {
        float sum = bias[t] + red[0][t] + red[1][t] + red[2][t] + red[3][t];
        out[b * Odim + t] = fmaxf(sum, 0.0f);
    }
}

// ---------------------------------------------------------------------------
extern "C" void kernel_launch(void* const* d_in, const int* in_sizes, int n_in,
                              void* d_out, int out_size) {
    const float* x    = (const float*)d_in[0];   // [256, 8192]
    const float* W    = (const float*)d_in[1];   // [8192, 32]
    const float* bias = (const float*)d_in[2];   // [32]
    float* out        = (float*)d_out;           // [256, 32]

    cudaFuncSetAttribute(k1_partial, cudaFuncAttributeMaxDynamicSharedMemorySize,
                         48 * 1024);

    dim3 g1(NBT, NCH);
    k1_partial<<<g1, 256, 48 * 1024>>>(x, W);
    k2_reduce<<<Bdim, 128>>>(bias, out);
    knop<<<1, 1>>>();   // keep ncu capture on position 0 = k1
}